// round 13
// baseline (speedup 1.0000x reference)
#include <cuda_runtime.h>
#include <math.h>
#include <stdint.h>

// ---------------------------------------------------------------------------
// GDER: out[b] = mean( Rx^2 + Ry^2 ) over valid 498x498 map.
// sum(Gy) is cancellation noise => Gy/sum(Gy) taps ~1e15 and Ry^2 dominates by
// >1e16 relative. Only the Gy path is computed, as a separable conv
// Gy = A(y)*B(x), 1/sum(Gy) folded into vertical taps. sum(Gy) replicated on
// host in numpy's exact f64 pairwise order (validated R1-R12, rel_err ~9e-8).
//
// R13: occupancy attack. 2 output cols/thread (ring 15 u64, not 30), 256
// threads/block, __launch_bounds__(256,3) => 24 warps/SM (was 16, regfile-
// pinned). Warp-uniform parity mapping pid = 2*(k&127)+(k>>7): warps 0-3 get
// even pairs (window offset 0, 4 LDG.128), warps 4-7 odd pairs (offset 2,
// 5 LDG.128) — no divergence, all compile-time indices. TILE=84/TILES_Y=6:
// 384 blocks = single wave at 3 blocks/SM, init overhead 18%.
// ---------------------------------------------------------------------------

#define NB        64
#define W         512
#define OUTW      498
#define TILE      84
#define TILES_Y   6        // 6*84 = 504 >= 498

typedef unsigned long long u64;

struct Weights {
    float hw[8];   // horizontal symmetric taps: hw[0..6] pair weights, hw[7] center
    float vw[7];   // vertical antisymmetric taps (scaled by 1/sum(Gy))
};

__device__ double g_partials[NB * TILES_Y];
__device__ int    g_count[NB];   // zero-initialized; self-resetting

// ---- f32x2 packed helpers (sm_100+) ----
__device__ __forceinline__ u64 pack2(float lo, float hi) {
    u64 r; asm("mov.b64 %0, {%1, %2};" : "=l"(r) : "f"(lo), "f"(hi)); return r;
}
__device__ __forceinline__ void unpack2(u64 v, float& lo, float& hi) {
    asm("mov.b64 {%0, %1}, %2;" : "=f"(lo), "=f"(hi) : "l"(v));
}
__device__ __forceinline__ u64 fma2(u64 a, u64 b, u64 c) {
    u64 d; asm("fma.rn.f32x2 %0, %1, %2, %3;" : "=l"(d) : "l"(a), "l"(b), "l"(c)); return d;
}
__device__ __forceinline__ u64 add2(u64 a, u64 b) {
    u64 d; asm("add.rn.f32x2 %0, %1, %2;" : "=l"(d) : "l"(a), "l"(b)); return d;
}
__device__ __forceinline__ u64 neg2(u64 a) { return a ^ 0x8000000080000000ull; }

__global__ __launch_bounds__(256, 3) void gder_kernel(const float* __restrict__ x,
                                                      Weights wt,
                                                      float* __restrict__ out)
{
    const int k     = threadIdx.x;
    const int tileY = blockIdx.x;
    const int batch = blockIdx.y;
    const int y0    = tileY * TILE;
    const float* __restrict__ img = x + (size_t)batch * W * W;

    __shared__ double red[256];

    // packed weights
    u64 hw2[8], vp[7];
    #pragma unroll
    for (int j = 0; j < 8; ++j) hw2[j] = pack2(wt.hw[j], wt.hw[j]);
    #pragma unroll
    for (int kk = 0; kk < 7; ++kk) vp[kk] = pack2(wt.vw[kk], wt.vw[kk]);
    #define HWM(j) (hw2[(j) < 8 ? (j) : 14 - (j)])

    // warp-uniform parity mapping: pid = 2*(k&127) + (k>>7)
    //   warps 0-3 (k<128): even pid, output cols (4j, 4j+1),   window off 0, 4 quads
    //   warps 4-7 (k>=128): odd pid,  output cols (4j+2, 4j+3), window off 2, 5 quads
    const int  j128    = k & 127;         // quad index j
    const bool oddHalf = (k >= 128);
    const int  pid     = 2 * j128 + (oddHalf ? 1 : 0);
    const bool valid   = (pid <= 248);    // output pair (2*pid, 2*pid+1) <= 497

    // in-bounds load base: even needs 4j+15<=511 (j<=124), odd 4j+19<=511 (j<=123);
    // over-limit threads are invalid and just need in-bounds addresses
    int cb = 4 * j128;
    if (oddHalf) { if (cb > 492) cb = 492; }
    else         { if (cb > 496) cb = 496; }

    const float* p = img + (size_t)y0 * W + cb;

    // window: even pairs (f[2m], f[2m+1]) are load register pairs (free f32x2)
    union InBuf { float f[20]; u64 d[10]; float4 v[5]; };
    InBuf in;

    u64 ring[15];     // horizontal results, slot s holds row (y0 + s) mod 15
    u64 fA = 0ull;

    #define LOAD4() do {                                          \
        in.v[0] = *reinterpret_cast<const float4*>(p);            \
        in.v[1] = *reinterpret_cast<const float4*>(p + 4);        \
        in.v[2] = *reinterpret_cast<const float4*>(p + 8);        \
        in.v[3] = *reinterpret_cast<const float4*>(p + 12);       \
    } while (0)
    #define LOAD5() do {                                          \
        LOAD4();                                                  \
        in.v[4] = *reinterpret_cast<const float4*>(p + 16);       \
    } while (0)

    #define UPAIR(idx) (((idx) & 1) ? pack2(in.f[idx], in.f[(idx) + 1]) : in.d[(idx) / 2])

    // horizontal for one packed output pair, split 8/7 chains; OFF = 0 or 2
    #define HORIZ_P(dst, OFF) do {                                \
        u64 h0 = 0ull, h1 = 0ull;                                 \
        _Pragma("unroll")                                         \
        for (int j = 0; j < 15; ++j) {                            \
            const u64 uj = UPAIR(j + (OFF));                      \
            if (j <= 7) h0 = fma2(HWM(j), uj, h0);                \
            else        h1 = fma2(HWM(j), uj, h1);                \
        }                                                         \
        dst = add2(h0, h1);                                       \
    } while (0)

    // vertical: oldest ring slot = q; accumulate square if valid
    #define VERTQ(q) do {                                         \
        u64 aA = 0ull, bA = 0ull;                                 \
        _Pragma("unroll")                                         \
        for (int kk = 0; kk < 7; ++kk) {                          \
            aA = fma2(vp[kk], ring[((q) + kk) % 15], aA);         \
            bA = fma2(vp[kk], ring[((q) + 14 - kk) % 15], bA);    \
        }                                                         \
        const u64 o = add2(aA, neg2(bA));                         \
        if (valid) fA = fma2(o, o, fA);                           \
    } while (0)

    // full pipeline: init 15 rows; 5 fast phases x 15 (i=1..75, provably
    // in-bounds for every tile: loads <= y0+89 <= 509, outputs <= y0+74 <=
    // 494); guarded epilogue 9 rows (binds only for tile 5, y0=420).
    #define PIPELINE(OFF, LOADM) do {                             \
        _Pragma("unroll")                                         \
        for (int j = 0; j < 15; ++j) {                            \
            LOADM();                                              \
            HORIZ_P(ring[j], OFF);                                \
            p += W;                                               \
        }                                                         \
        _Pragma("unroll 1")                                       \
        for (int g = 0; g < 5; ++g) {                             \
            _Pragma("unroll")                                     \
            for (int q = 0; q < 15; ++q) {                        \
                LOADM();                                          \
                p += W;                                           \
                VERTQ(q);                  /* output y0+15g+q */  \
                HORIZ_P(ring[q], OFF);     /* row y0+15+15g+q */  \
            }                                                     \
        }                                                         \
        _Pragma("unroll")                                         \
        for (int q = 0; q < 9; ++q) {                             \
            const bool dl = (y0 + 90 + q < W);                    \
            const bool dv = (y0 + 75 + q < OUTW);                 \
            if (dl) LOADM();                                      \
            p += W;                                               \
            if (dv) VERTQ(q);              /* output y0+75+q */   \
            if (dl) HORIZ_P(ring[q], OFF); /* row y0+90+q */      \
        }                                                         \
    } while (0)

    if (!oddHalf) {
        PIPELINE(0, LOAD4);
    } else {
        PIPELINE(2, LOAD5);
    }

    // deterministic block reduction in double
    {
        float flo, fhi;
        unpack2(fA, flo, fhi);
        red[k] = (double)flo + (double)fhi;
    }
    __syncthreads();
    #pragma unroll
    for (int s = 128; s > 0; s >>= 1) {
        if (k < s) red[k] += red[k + s];
        __syncthreads();
    }
    if (k == 0) {
        g_partials[batch * TILES_Y + tileY] = red[0];
        __threadfence();
        const int old = atomicAdd(&g_count[batch], 1);
        if (old == TILES_Y - 1) {   // last block for this batch: fixed-order sum
            __threadfence();
            double s = 0.0;
            #pragma unroll
            for (int i = 0; i < TILES_Y; ++i)
                s += __ldcg(&g_partials[batch * TILES_Y + i]);
            out[batch] = (float)(s * (1.0 / ((double)OUTW * (double)OUTW)));
            g_count[batch] = 0;     // reset for next graph replay
        }
    }
}

// ---------------------------------------------------------------------------
// Host side: replicate numpy float64 semantics exactly (validated R1-R12).
// ---------------------------------------------------------------------------

// numpy's pairwise_sum for contiguous float64 (PW_BLOCKSIZE = 128)
static double np_pairwise(const double* a, int n)
{
    if (n < 8) {
        double res = 0.0;
        for (int i = 0; i < n; ++i) res += a[i];
        return res;
    }
    else if (n <= 128) {
        double r[8];
        for (int j = 0; j < 8; ++j) r[j] = a[j];
        int i;
        for (i = 8; i < n - (n % 8); i += 8)
            for (int j = 0; j < 8; ++j) r[j] += a[i + j];
        double res = ((r[0] + r[1]) + (r[2] + r[3])) + ((r[4] + r[5]) + (r[6] + r[7]));
        for (; i < n; ++i) res += a[i];
        return res;
    }
    else {
        int n2 = n / 2;
        n2 -= n2 % 8;
        return np_pairwise(a, n2) + np_pairwise(a + n2, n - n2);
    }
}

extern "C" void kernel_launch(void* const* d_in, const int* in_sizes, int n_in,
                              void* d_out, int out_size)
{
    (void)in_sizes; (void)n_in; (void)out_size;
    const float* x  = (const float*)d_in[0];
    float*      out = (float*)d_out;

    const double sig     = 7.0 / 2.5;              // N=15//2=7; sig = N/2.5
    const double sig2    = pow(sig, 2.0);          // sig ** 2 (CPython float_pow -> libm pow)
    const double twosig2 = 2.0 * sig2;
    const double denomG  = (2.0 * M_PI) * sig;

    double Gy[225];
    for (int i = 0; i < 15; ++i) {
        const int yy = i - 7;
        for (int j = 0; j < 15; ++j) {
            const int xx = j - 7;
            const double G = exp((double)(-(xx * xx + yy * yy)) / twosig2) / denomG;
            Gy[i * 15 + j] = ((double)(-yy) * G) / sig2;
        }
    }
    const double s = np_pairwise(Gy, 225);         // np.sum(Gy), numpy pairwise order

    Weights wt;
    for (int j = 0; j < 8; ++j) {
        const int xx = j - 7;
        wt.hw[j] = (float)(exp((double)(-(xx * xx)) / twosig2) / denomG);
    }
    for (int kk = 0; kk < 7; ++kk) {
        const int yy = kk - 7;
        const double A = (((double)(-yy) * exp((double)(-(yy * yy)) / twosig2)) / sig2) / s;
        wt.vw[kk] = (float)A;
    }

    dim3 grid(TILES_Y, NB);
    gder_kernel<<<grid, 256>>>(x, wt, out);
}

// round 14
// speedup vs baseline: 1.2985x; 1.2985x over previous
#include <cuda_runtime.h>
#include <math.h>
#include <stdint.h>

// ---------------------------------------------------------------------------
// GDER: out[b] = mean( Rx^2 + Ry^2 ) over valid 498x498 map.
// sum(Gy) is cancellation noise => Gy/sum(Gy) taps ~1e15 and Ry^2 dominates by
// >1e16 relative. Only the Gy path is computed, as a separable conv
// Gy = A(y)*B(x), 1/sum(Gy) folded into vertical taps. sum(Gy) replicated on
// host in numpy's exact f64 pairwise order (validated R1-R13, rel_err ~9e-8).
//
// R14 = R11 exchange-free structure + DISTANCE-2 double-buffered prefetch:
// loads for row r+16 issue at iteration r, consumed by HORIZ at iteration r+1
// (lag > DRAM 577cyc). Two window buffers alternate by row parity (static
// under full unroll). __launch_bounds__(128,3), TILE=84/TILES_Y=6: 384 blocks,
// single wave, ~142 regs (no spill under the 170 cap).
// ---------------------------------------------------------------------------

#define NB        64
#define W         512
#define OUTW      498
#define TILE      84
#define TILES_Y   6        // 6*84 = 504 >= 498

typedef unsigned long long u64;

struct Weights {
    float hw[8];   // horizontal symmetric taps: hw[0..6] pair weights, hw[7] center
    float vw[7];   // vertical antisymmetric taps (scaled by 1/sum(Gy))
};

__device__ double g_partials[NB * TILES_Y];
__device__ int    g_count[NB];   // zero-initialized; self-resetting

// ---- f32x2 packed helpers (sm_100+) ----
__device__ __forceinline__ u64 pack2(float lo, float hi) {
    u64 r; asm("mov.b64 %0, {%1, %2};" : "=l"(r) : "f"(lo), "f"(hi)); return r;
}
__device__ __forceinline__ void unpack2(u64 v, float& lo, float& hi) {
    asm("mov.b64 {%0, %1}, %2;" : "=f"(lo), "=f"(hi) : "l"(v));
}
__device__ __forceinline__ u64 fma2(u64 a, u64 b, u64 c) {
    u64 d; asm("fma.rn.f32x2 %0, %1, %2, %3;" : "=l"(d) : "l"(a), "l"(b), "l"(c)); return d;
}
__device__ __forceinline__ u64 add2(u64 a, u64 b) {
    u64 d; asm("add.rn.f32x2 %0, %1, %2;" : "=l"(d) : "l"(a), "l"(b)); return d;
}
__device__ __forceinline__ u64 neg2(u64 a) { return a ^ 0x8000000080000000ull; }

__global__ __launch_bounds__(128, 3) void gder_kernel(const float* __restrict__ x,
                                                      Weights wt,
                                                      float* __restrict__ out)
{
    const int t     = threadIdx.x;
    const int tileY = blockIdx.x;
    const int batch = blockIdx.y;
    const int y0    = tileY * TILE;
    const float* __restrict__ img = x + (size_t)batch * W * W;

    __shared__ double red[128];

    // packed weights
    u64 hw2[8], vp[7];
    #pragma unroll
    for (int j = 0; j < 8; ++j) hw2[j] = pack2(wt.hw[j], wt.hw[j]);
    #pragma unroll
    for (int k = 0; k < 7; ++k) vp[k] = pack2(wt.vw[k], wt.vw[k]);
    #define HWM(j) (hw2[(j) < 8 ? (j) : 14 - (j)])

    const int c = 4 * t;   // this thread's 4 output columns c..c+3

    // Edge handling at init only (validated R10-R11):
    //  t <= 123: cb = c, 5 loads.   t == 124: cb = 496, 4 loads, f[16..19]=0
    //  (feeds only masked outputs). t >= 125: cb = 492, outputs fully masked.
    const int  cb  = (c <= 496) ? c : 492;
    const bool do5 = (c != 496);

    // output validity masks (packed pairs A=(c,c+1), B=(c+2,c+3))
    const u64 LOm = 0x00000000FFFFFFFFull, HIm = 0xFFFFFFFF00000000ull;
    const u64 mA = (c     <= 497 ? LOm : 0ull) | (c + 1 <= 497 ? HIm : 0ull);
    const u64 mB = (c + 2 <= 497 ? LOm : 0ull) | (c + 3 <= 497 ? HIm : 0ull);

    // walking row pointer: immediate-offset LDG.128s, +W per row
    const float* p = img + (size_t)y0 * W + cb;

    // TWO window buffers (distance-2 prefetch), alternating by row parity;
    // even pairs (f[2m], f[2m+1]) are load register pairs (free f32x2)
    union InBuf { float f[20]; u64 d[10]; float4 v[5]; };
    InBuf bA, bB;
    bA.f[16] = 0.f; bA.f[17] = 0.f; bA.f[18] = 0.f; bA.f[19] = 0.f;
    bB.f[16] = 0.f; bB.f[17] = 0.f; bB.f[18] = 0.f; bB.f[19] = 0.f;

    #define LOADU(B) do {                                             \
        (B).v[0] = *reinterpret_cast<const float4*>(p);               \
        (B).v[1] = *reinterpret_cast<const float4*>(p + 4);           \
        (B).v[2] = *reinterpret_cast<const float4*>(p + 8);           \
        (B).v[3] = *reinterpret_cast<const float4*>(p + 12);          \
        if (do5) (B).v[4] = *reinterpret_cast<const float4*>(p + 16); \
    } while (0)

    #define UPAIRB(B, idx) (((idx) & 1) ? pack2((B).f[idx], (B).f[(idx) + 1]) \
                                        : (B).d[(idx) / 2])

    // horizontal from buffer B into ring pair (hA, hB_), split 8/7 chains
    #define HORIZB(B, hA, hB_) do {                                   \
        u64 hA0 = 0ull, hA1 = 0ull, hB0 = 0ull, hB1 = 0ull;           \
        _Pragma("unroll")                                             \
        for (int j = 0; j < 15; ++j) {                                \
            const u64 uj = UPAIRB(B, j);                              \
            if (j <= 7) hA0 = fma2(HWM(j), uj, hA0);                  \
            else        hA1 = fma2(HWM(j), uj, hA1);                  \
        }                                                             \
        _Pragma("unroll")                                             \
        for (int j = 0; j < 15; ++j) {                                \
            const u64 uj = UPAIRB(B, j + 2);                          \
            if (j <= 7) hB0 = fma2(HWM(j), uj, hB0);                  \
            else        hB1 = fma2(HWM(j), uj, hB1);                  \
        }                                                             \
        hA = add2(hA0, hA1);                                          \
        hB_ = add2(hB0, hB1);                                         \
    } while (0)

    // vertical: ring slots q..q+14 hold rows y0+i..y0+i+14 (q = i mod 15)
    #define VERTQ(q) do {                                             \
        u64 aA = 0ull, bAc = 0ull, aB = 0ull, bBc = 0ull;             \
        _Pragma("unroll")                                             \
        for (int k = 0; k < 7; ++k) {                                 \
            aA  = fma2(vp[k], rA[((q) + k) % 15], aA);                \
            bAc = fma2(vp[k], rA[((q) + 14 - k) % 15], bAc);          \
            aB  = fma2(vp[k], rB[((q) + k) % 15], aB);                \
            bBc = fma2(vp[k], rB[((q) + 14 - k) % 15], bBc);          \
        }                                                             \
        u64 oA = add2(aA, neg2(bAc));                                 \
        u64 oB = add2(aB, neg2(bBc));                                 \
        if (t >= 124) { oA &= mA; oB &= mB; }                         \
        fA = fma2(oA, oA, fA);                                        \
        fB = fma2(oB, oB, fB);                                        \
    } while (0)

    // ring: slot j holds row y0+j (mod 15)
    u64 rA[15], rB[15];

    // init: rows y0..y0+14 (always valid: y0+14 <= 434), buffer by row parity
    #pragma unroll
    for (int j = 0; j < 15; ++j) {
        if (j & 1) { LOADU(bB); HORIZB(bB, rA[j], rB[j]); }
        else       { LOADU(bA); HORIZB(bA, rA[j], rB[j]); }
        p += W;
    }
    // preload row y0+15 (parity 1 -> bB; always valid: y0+15 <= 435)
    LOADU(bB);
    p += W;

    u64 fA = 0ull, fB = 0ull;

    // fast iterations i = 0..74: provably in-bounds for EVERY tile
    // (loads row y0+16+i <= 420+16+74 = 510 < 512; outputs y0+i <= 494 < 498).
    // Iter i: load row y0+16+i -> buffer (i&1); VERT output y0+i;
    // HORIZ row y0+15+i from buffer !(i&1) into slot i%15.
    #pragma unroll
    for (int i = 0; i < 75; ++i) {
        if (i & 1) { LOADU(bB); } else { LOADU(bA); }
        p += W;
        VERTQ(i % 15);
        if (i & 1) { HORIZB(bA, rA[i % 15], rB[i % 15]); }
        else       { HORIZB(bB, rA[i % 15], rB[i % 15]); }
    }

    // epilogue i = 75..83 (guards bind only for tile 5, y0 = 420):
    //  load guard:   y0+16+i < 512   (stale buffer feeds only rows >= 512)
    //  insert guard: y0+15+i < 512   (stale ring rows feed only outputs >= 498)
    //  output guard: y0+i    < 498
    #pragma unroll
    for (int e = 0; e < 9; ++e) {
        const int i = 75 + e;
        const bool dl = (y0 + 16 + i < W);
        const bool di = (y0 + 15 + i < W);
        const bool dv = (y0 + i < OUTW);
        if (dl) { if (i & 1) { LOADU(bB); } else { LOADU(bA); } }
        p += W;
        if (dv) VERTQ(i % 15);
        if (di) {
            if (i & 1) { HORIZB(bA, rA[i % 15], rB[i % 15]); }
            else       { HORIZB(bB, rA[i % 15], rB[i % 15]); }
        }
    }

    // deterministic block reduction in double
    {
        const u64 facc = add2(fA, fB);
        float flo, fhi;
        unpack2(facc, flo, fhi);
        red[t] = (double)flo + (double)fhi;
    }
    __syncthreads();
    #pragma unroll
    for (int s = 64; s > 0; s >>= 1) {
        if (t < s) red[t] += red[t + s];
        __syncthreads();
    }
    if (t == 0) {
        g_partials[batch * TILES_Y + tileY] = red[0];
        __threadfence();
        const int old = atomicAdd(&g_count[batch], 1);
        if (old == TILES_Y - 1) {   // last block for this batch: fixed-order sum
            __threadfence();
            double s = 0.0;
            #pragma unroll
            for (int i = 0; i < TILES_Y; ++i)
                s += __ldcg(&g_partials[batch * TILES_Y + i]);
            out[batch] = (float)(s * (1.0 / ((double)OUTW * (double)OUTW)));
            g_count[batch] = 0;     // reset for next graph replay
        }
    }
}

// ---------------------------------------------------------------------------
// Host side: replicate numpy float64 semantics exactly (validated R1-R13).
// ---------------------------------------------------------------------------

// numpy's pairwise_sum for contiguous float64 (PW_BLOCKSIZE = 128)
static double np_pairwise(const double* a, int n)
{
    if (n < 8) {
        double res = 0.0;
        for (int i = 0; i < n; ++i) res += a[i];
        return res;
    }
    else if (n <= 128) {
        double r[8];
        for (int j = 0; j < 8; ++j) r[j] = a[j];
        int i;
        for (i = 8; i < n - (n % 8); i += 8)
            for (int j = 0; j < 8; ++j) r[j] += a[i + j];
        double res = ((r[0] + r[1]) + (r[2] + r[3])) + ((r[4] + r[5]) + (r[6] + r[7]));
        for (; i < n; ++i) res += a[i];
        return res;
    }
    else {
        int n2 = n / 2;
        n2 -= n2 % 8;
        return np_pairwise(a, n2) + np_pairwise(a + n2, n - n2);
    }
}

extern "C" void kernel_launch(void* const* d_in, const int* in_sizes, int n_in,
                              void* d_out, int out_size)
{
    (void)in_sizes; (void)n_in; (void)out_size;
    const float* x  = (const float*)d_in[0];
    float*      out = (float*)d_out;

    const double sig     = 7.0 / 2.5;              // N=15//2=7; sig = N/2.5
    const double sig2    = pow(sig, 2.0);          // sig ** 2 (CPython float_pow -> libm pow)
    const double twosig2 = 2.0 * sig2;
    const double denomG  = (2.0 * M_PI) * sig;

    double Gy[225];
    for (int i = 0; i < 15; ++i) {
        const int yy = i - 7;
        for (int j = 0; j < 15; ++j) {
            const int xx = j - 7;
            const double G = exp((double)(-(xx * xx + yy * yy)) / twosig2) / denomG;
            Gy[i * 15 + j] = ((double)(-yy) * G) / sig2;
        }
    }
    const double s = np_pairwise(Gy, 225);         // np.sum(Gy), numpy pairwise order

    Weights wt;
    for (int j = 0; j < 8; ++j) {
        const int xx = j - 7;
        wt.hw[j] = (float)(exp((double)(-(xx * xx)) / twosig2) / denomG);
    }
    for (int k = 0; k < 7; ++k) {
        const int yy = k - 7;
        const double A = (((double)(-yy) * exp((double)(-(yy * yy)) / twosig2)) / sig2) / s;
        wt.vw[k] = (float)A;
    }

    dim3 grid(TILES_Y, NB);
    gder_kernel<<<grid, 128>>>(x, wt, out);
}